// round 2
// baseline (speedup 1.0000x reference)
#include <cuda_runtime.h>

#define N_NODES 50000
#define N_EDGES 800000
#define AD 128
#define BD 16
#define HID 128
#define CDIM 256   // BD*BD

// ---------------- static device scratch (no allocations allowed) ----------------
__device__ int   g_is64;
__device__ int   g_nbr[N_EDGES];
__device__ int   g_off[N_NODES + 1];
__device__ float g_S[N_NODES * BD];     // per-node neighbor-bond sums
__device__ float g_agg[N_NODES * BD];   // aggregate = A[v] @ S[v]

// ---- packed fp32x2 helpers (Blackwell FFMA2 — 2x fp32 throughput, PTX-only) ----
typedef unsigned long long u64;

__device__ __forceinline__ u64 pack2(float lo, float hi) {
    return (u64)__float_as_uint(lo) | ((u64)__float_as_uint(hi) << 32);
}
__device__ __forceinline__ float lo2(u64 v) { return __uint_as_float((unsigned)(v & 0xffffffffu)); }
__device__ __forceinline__ float hi2(u64 v) { return __uint_as_float((unsigned)(v >> 32)); }

#define FFMA2(d, a, b) \
    asm("fma.rn.f32x2 %0, %1, %2, %0;" : "+l"(d) : "l"(a), "l"(b))

// ---------------- kernel 0: detect int64 vs int32 pairs ----------------
// int64 layout: odd 32-bit words are high halves of values < 50000 -> all zero.
// int32 layout: odd words are nbr indices (random, nonzero w.h.p. over 1024 samples).
__global__ void k_detect(const unsigned int* __restrict__ w) {
    __shared__ int nz;
    if (threadIdx.x == 0) nz = 0;
    __syncthreads();
    int local = 0;
    for (int i = threadIdx.x; i < 1024; i += blockDim.x)
        if (w[2 * i + 1] != 0u) local = 1;
    if (local) atomicOr(&nz, 1);
    __syncthreads();
    if (threadIdx.x == 0) g_is64 = (nz == 0) ? 1 : 0;
}

// ---------------- kernel 1: extract nbr column as int32 ----------------
__global__ void k_convert(const void* __restrict__ pairs) {
    int e = blockIdx.x * 256 + threadIdx.x;
    if (e >= N_EDGES) return;
    if (g_is64)
        g_nbr[e] = (int)((const long long*)pairs)[2 * (size_t)e + 1];
    else
        g_nbr[e] = ((const int*)pairs)[2 * (size_t)e + 1];
}

// ---------------- kernel 2: CSR offsets via binary search (src sorted) ----------------
__global__ void k_off(const void* __restrict__ pairs) {
    int v = blockIdx.x * 256 + threadIdx.x;
    if (v > N_NODES) return;
    const long long* p64 = (const long long*)pairs;
    const int*       p32 = (const int*)pairs;
    const bool is64 = (g_is64 != 0);
    int lo = 0, hi = N_EDGES;
    while (lo < hi) {
        int mid = (lo + hi) >> 1;
        long long s = is64 ? p64[2 * (size_t)mid] : (long long)p32[2 * (size_t)mid];
        if (s < (long long)v) lo = mid + 1; else hi = mid;
    }
    g_off[v] = lo;
}

// ---------------- kernel 3: S[v] = sum over edges of v of bonds[nbr] ----------------
// one warp per node; 2 half-warps process 2 edges/iter, 16 lanes per bond row.
__global__ void k_S(const float* __restrict__ bonds) {
    int w    = (blockIdx.x * blockDim.x + threadIdx.x) >> 5;
    int lane = threadIdx.x & 31;
    if (w >= N_NODES) return;
    int e0 = g_off[w], e1 = g_off[w + 1];
    int h = lane >> 4, j = lane & 15;
    float acc = 0.f;
    for (int e = e0 + h; e < e1; e += 2)
        acc += bonds[(size_t)g_nbr[e] * BD + j];
    acc += __shfl_down_sync(0xffffffffu, acc, 16);
    if (lane < 16) g_S[(size_t)w * BD + j] = acc;
}

// ---------------- kernel 4: fused GEMM A = atoms@K + bias, then agg = A@S ----------------
// tile 128 nodes x 128 cols, 256 threads, 8x8 microtile with FFMA2.
#define MT 128
#define NT 128
#define KC 16

__global__ __launch_bounds__(256, 2)
void k_gemm(const float* __restrict__ atoms,
            const float* __restrict__ Kmat,
            const float* __restrict__ bias) {
    __shared__ float As[KC][MT + 4];   // transposed [k][m]
    __shared__ float Bs[KC][NT];
    __shared__ float Ss[MT][BD];

    int t  = threadIdx.x;
    int tx = t & 15, ty = t >> 4;
    int v0 = blockIdx.x * MT;
    int n0 = blockIdx.y * NT;

    // stage S tile (visible after first __syncthreads in main loop)
    #pragma unroll
    for (int q = 0; q < 8; q++) {
        int idx = q * 256 + t;            // 0..2047
        int m = idx >> 4, j = idx & 15;
        float s = 0.f;
        if (v0 + m < N_NODES) s = g_S[(size_t)(v0 + m) * BD + j];
        Ss[m][j] = s;
    }

    u64 acc2[8][4];
    #pragma unroll
    for (int i = 0; i < 8; i++)
        #pragma unroll
        for (int j = 0; j < 4; j++) acc2[i][j] = 0ull;

    for (int kc = 0; kc < AD; kc += KC) {
        // A tile (transposed store)
        #pragma unroll
        for (int q = 0; q < 2; q++) {
            int idx = t * 2 + q;          // 0..511
            int mi = idx >> 2;            // 0..127
            int k4 = (idx & 3) * 4;
            float4 f = make_float4(0.f, 0.f, 0.f, 0.f);
            if (v0 + mi < N_NODES)
                f = *(const float4*)&atoms[(size_t)(v0 + mi) * AD + kc + k4];
            As[k4 + 0][mi] = f.x; As[k4 + 1][mi] = f.y;
            As[k4 + 2][mi] = f.z; As[k4 + 3][mi] = f.w;
        }
        // B tile
        #pragma unroll
        for (int q = 0; q < 2; q++) {
            int idx = t * 2 + q;          // 0..511
            int kk = idx >> 5;            // 0..15
            int n4 = (idx & 31) * 4;      // 0..124
            *(float4*)&Bs[kk][n4] =
                *(const float4*)&Kmat[(size_t)(kc + kk) * CDIM + n0 + n4];
        }
        __syncthreads();

        #pragma unroll
        for (int kk = 0; kk < KC; kk++) {
            float4 a0 = *(float4*)&As[kk][ty * 8];
            float4 a1 = *(float4*)&As[kk][ty * 8 + 4];
            float4 b0 = *(float4*)&Bs[kk][tx * 8];
            float4 b1 = *(float4*)&Bs[kk][tx * 8 + 4];
            float  a[8] = {a0.x, a0.y, a0.z, a0.w, a1.x, a1.y, a1.z, a1.w};
            u64 bv[4];
            bv[0] = pack2(b0.x, b0.y); bv[1] = pack2(b0.z, b0.w);
            bv[2] = pack2(b1.x, b1.y); bv[3] = pack2(b1.z, b1.w);
            #pragma unroll
            for (int i = 0; i < 8; i++) {
                u64 av = pack2(a[i], a[i]);
                #pragma unroll
                for (int j = 0; j < 4; j++) FFMA2(acc2[i][j], av, bv[j]);
            }
        }
        __syncthreads();
    }

    // bias (zeros in the dataset, but honor the reference) — add to accumulators
    float bvals[8];
    #pragma unroll
    for (int j = 0; j < 8; j++) bvals[j] = bias[n0 + tx * 8 + j];

    // contract with S over this thread's 8-wide j-half; pair-reduce adjacent lanes
    int jb = (tx & 1) * 8;      // which half of the 16 j's
    int il = tx >> 1;           // local i (0..7)
    #pragma unroll
    for (int i = 0; i < 8; i++) {
        int m = ty * 8 + i;
        float p = 0.f;
        #pragma unroll
        for (int j = 0; j < 4; j++) {
            float cx = lo2(acc2[i][j]) + bvals[2 * j];
            float cy = hi2(acc2[i][j]) + bvals[2 * j + 1];
            p += cx * Ss[m][jb + 2 * j];
            p += cy * Ss[m][jb + 2 * j + 1];
        }
        float r = p + __shfl_down_sync(0xffffffffu, p, 1);
        if ((tx & 1) == 0 && v0 + m < N_NODES)
            g_agg[(size_t)(v0 + m) * BD + blockIdx.y * 8 + il] = r;
    }
}

// ---------------- kernel 5: out = relu(agg@Wn + relu(bonds@Wi)), replicated x4 ----------------
__global__ void k_final(const float* __restrict__ bonds,
                        const float* __restrict__ Wn,
                        const float* __restrict__ Wi,
                        float* __restrict__ out) {
    int h   = threadIdx.x & 127;
    int sub = threadIdx.x >> 7;       // 0 or 1
    int v0  = blockIdx.x * 16;
    float wn[16], wi[16];
    #pragma unroll
    for (int i = 0; i < 16; i++) {
        wn[i] = Wn[i * HID + h];
        wi[i] = Wi[i * HID + h];
    }
    const size_t slab = (size_t)N_NODES * HID;
    for (int q = 0; q < 8; q++) {
        int v = v0 + sub * 8 + q;
        if (v >= N_NODES) break;
        float nodes = 0.f, edge = 0.f;
        #pragma unroll
        for (int i = 0; i < 16; i++) {
            nodes += g_agg[(size_t)v * BD + i] * wn[i];
            edge  += __ldg(&bonds[(size_t)v * BD + i]) * wi[i];
        }
        edge = fmaxf(edge, 0.f);
        float r = fmaxf(nodes + edge, 0.f);
        size_t base = (size_t)v * HID + h;
        out[base]            = r;
        out[base + slab]     = r;
        out[base + 2 * slab] = r;
        out[base + 3 * slab] = r;
    }
}

// ---------------- launch ----------------
extern "C" void kernel_launch(void* const* d_in, const int* in_sizes, int n_in,
                              void* d_out, int out_size) {
    const float* atoms = (const float*)d_in[0];
    const float* bonds = (const float*)d_in[1];
    const void*  pairs = d_in[2];
    const float* Kmat  = (const float*)d_in[3];
    const float* bias  = (const float*)d_in[4];
    const float* Wn    = (const float*)d_in[5];
    const float* Wi    = (const float*)d_in[6];
    float* out = (float*)d_out;

    k_detect<<<1, 256>>>((const unsigned int*)pairs);
    k_convert<<<(N_EDGES + 255) / 256, 256>>>(pairs);
    k_off<<<(N_NODES + 256) / 256, 256>>>(pairs);
    k_S<<<N_NODES / 8, 256>>>(bonds);
    dim3 g3((N_NODES + MT - 1) / MT, CDIM / NT);
    k_gemm<<<g3, 256>>>(atoms, Kmat, bias);
    k_final<<<(N_NODES + 15) / 16, 256>>>(bonds, Wn, Wi, out);
}

// round 17
// speedup vs baseline: 1.3866x; 1.3866x over previous
#include <cuda_runtime.h>
#include <cuda_bf16.h>
#include <cstdint>

#define N_NODES 50000
#define N_EDGES 800000
#define AD 128
#define BD 16
#define HID 128
#define CDIM 256   // BD*BD

// ---------------- static device scratch ----------------
__device__ int   g_is64;
__device__ int   g_nbr[N_EDGES];
__device__ int   g_off[N_NODES + 1];
__device__ float g_S[N_NODES * BD];
__device__ float g_agg[N_NODES * BD];

// ================= helpers =================
__device__ __forceinline__ uint32_t smem_u32(const void* p) {
    uint32_t a;
    asm("{ .reg .u64 t; cvta.to.shared.u64 t, %1; cvt.u32.u64 %0, t; }" : "=r"(a) : "l"(p));
    return a;
}

// portable (sm_80+) warp-level tensor ops — legal on plain sm_103 target
#define LDM_X4(r0, r1, r2, r3, addr) \
    asm volatile("ldmatrix.sync.aligned.m8n8.x4.shared.b16 {%0,%1,%2,%3}, [%4];" \
        : "=r"(r0), "=r"(r1), "=r"(r2), "=r"(r3) : "r"(addr))
#define LDM_X2(r0, r1, addr) \
    asm volatile("ldmatrix.sync.aligned.m8n8.x2.shared.b16 {%0,%1}, [%2];" \
        : "=r"(r0), "=r"(r1) : "r"(addr))
#define MMA_BF16(c, a, b) \
    asm volatile("mma.sync.aligned.m16n8k16.row.col.f32.bf16.bf16.f32 " \
        "{%0,%1,%2,%3}, {%4,%5,%6,%7}, {%8,%9}, {%0,%1,%2,%3};" \
        : "+f"((c)[0]), "+f"((c)[1]), "+f"((c)[2]), "+f"((c)[3]) \
        : "r"((a)[0]), "r"((a)[1]), "r"((a)[2]), "r"((a)[3]), "r"((b)[0]), "r"((b)[1]))

// fp32 -> bf16 hi/lo split, two elements packed per u32
__device__ __forceinline__ void split2(float a, float b, uint32_t& hi, uint32_t& lo) {
    __nv_bfloat16 ah = __float2bfloat16(a), bh = __float2bfloat16(b);
    __nv_bfloat16 al = __float2bfloat16(a - __bfloat162float(ah));
    __nv_bfloat16 bl = __float2bfloat16(b - __bfloat162float(bh));
    hi = (uint32_t)__bfloat16_as_ushort(ah) | ((uint32_t)__bfloat16_as_ushort(bh) << 16);
    lo = (uint32_t)__bfloat16_as_ushort(al) | ((uint32_t)__bfloat16_as_ushort(bl) << 16);
}

// ---------------- kernel 0: detect int64 vs int32 pairs ----------------
__global__ void k_detect(const unsigned int* __restrict__ w) {
    __shared__ int nz;
    if (threadIdx.x == 0) nz = 0;
    __syncthreads();
    int local = 0;
    for (int i = threadIdx.x; i < 1024; i += blockDim.x)
        if (w[2 * i + 1] != 0u) local = 1;
    if (local) atomicOr(&nz, 1);
    __syncthreads();
    if (threadIdx.x == 0) g_is64 = (nz == 0) ? 1 : 0;
}

// ---------------- kernel 1: extract nbr column as int32 ----------------
__global__ void k_convert(const void* __restrict__ pairs) {
    int e = blockIdx.x * 256 + threadIdx.x;
    if (e >= N_EDGES) return;
    if (g_is64)
        g_nbr[e] = (int)((const long long*)pairs)[2 * (size_t)e + 1];
    else
        g_nbr[e] = ((const int*)pairs)[2 * (size_t)e + 1];
}

// ---------------- kernel 2: CSR offsets via binary search ----------------
__global__ void k_off(const void* __restrict__ pairs) {
    int v = blockIdx.x * 256 + threadIdx.x;
    if (v > N_NODES) return;
    const long long* p64 = (const long long*)pairs;
    const int*       p32 = (const int*)pairs;
    const bool is64 = (g_is64 != 0);
    int lo = 0, hi = N_EDGES;
    while (lo < hi) {
        int mid = (lo + hi) >> 1;
        long long s = is64 ? p64[2 * (size_t)mid] : (long long)p32[2 * (size_t)mid];
        if (s < (long long)v) lo = mid + 1; else hi = mid;
    }
    g_off[v] = lo;
}

// ---------------- kernel 3: S[v] = sum of bonds[nbr] over edges of v ----------------
// one warp per node; 2 half-warps, edge loop unrolled x2 -> MLP=4 per warp.
__global__ void k_S(const float* __restrict__ bonds) {
    int w    = (blockIdx.x * blockDim.x + threadIdx.x) >> 5;
    int lane = threadIdx.x & 31;
    if (w >= N_NODES) return;
    int e0 = g_off[w], e1 = g_off[w + 1];
    int h = lane >> 4, j = lane & 15;
    float acc0 = 0.f, acc1 = 0.f;
    int e = e0 + h;
    for (; e + 2 < e1; e += 4) {
        int n0 = g_nbr[e];
        int n1 = g_nbr[e + 2];
        acc0 += bonds[(size_t)n0 * BD + j];
        acc1 += bonds[(size_t)n1 * BD + j];
    }
    if (e < e1) acc0 += bonds[(size_t)g_nbr[e] * BD + j];
    float acc = acc0 + acc1;
    acc += __shfl_down_sync(0xffffffffu, acc, 16);
    if (lane < 16) g_S[(size_t)w * BD + j] = acc;
}

// ---------------- kernel 4: mma.sync bf16 GEMM + S contraction ----------------
// per block: C(128x128) = atoms_tile(128x128) @ Kmat_tile(128x128) via bf16
// hi/lo split, 3 passes (AhBh + AhBl + AlBh) into fp32 accumulators; then
// agg[v, i] = sum_j (C[v, i*16+j] + bias) * S[v, j] for this block's 8 i's.
// smem tiles: [rows][136 bf16] (272 B row stride) -> ldmatrix conflict-free.
#define RSTR   272              // bytes per row (136 bf16)
#define SA_HI  0
#define SA_LO  34816
#define SB_HI  69632
#define SB_LO  104448
#define SM_SS  139264           // float[128][17] = 8704 B
#define SM_BS  147968           // float[128]
#define SM_TOTAL 148480

__global__ __launch_bounds__(256, 1)
void k_gemm_mma(const float* __restrict__ atoms,
                const float* __restrict__ Kmat,
                const float* __restrict__ bias) {
    extern __shared__ char smem[];
    uint32_t sb = smem_u32(smem);
    int t = threadIdx.x;
    int wid = t >> 5, lane = t & 31;
    int v0 = blockIdx.x * 128;
    int gy = blockIdx.y;            // n-half of CDIM: columns gy*128 .. +127

    float* Ss = (float*)(smem + SM_SS);
    float* bs = (float*)(smem + SM_BS);
    if (t < 128) bs[t] = bias[gy * 128 + t];

    // stage S tile (padded 17)
    #pragma unroll
    for (int q = 0; q < 8; q++) {
        int idx = q * 256 + t;
        int m = idx >> 4, j = idx & 15;
        float s = (v0 + m < N_NODES) ? g_S[(size_t)(v0 + m) * BD + j] : 0.f;
        Ss[m * 17 + j] = s;
    }

    // stage A: atoms[v0+m][k] -> bf16 hi/lo at [m][k]
    #pragma unroll
    for (int it = 0; it < 8; it++) {
        int idx = it * 256 + t;
        int m = idx >> 4;
        int c0 = (idx & 15) * 8;
        float x[8];
        if (v0 + m < N_NODES) {
            float4 f0 = *(const float4*)&atoms[(size_t)(v0 + m) * AD + c0];
            float4 f1 = *(const float4*)&atoms[(size_t)(v0 + m) * AD + c0 + 4];
            x[0]=f0.x; x[1]=f0.y; x[2]=f0.z; x[3]=f0.w;
            x[4]=f1.x; x[5]=f1.y; x[6]=f1.z; x[7]=f1.w;
        } else {
            #pragma unroll
            for (int i = 0; i < 8; i++) x[i] = 0.f;
        }
        uint32_t hi[4], lo[4];
        #pragma unroll
        for (int p = 0; p < 4; p++) split2(x[2*p], x[2*p+1], hi[p], lo[p]);
        uint32_t off = (uint32_t)m * RSTR + (uint32_t)c0 * 2;
        *(uint4*)(smem + SA_HI + off) = make_uint4(hi[0], hi[1], hi[2], hi[3]);
        *(uint4*)(smem + SA_LO + off) = make_uint4(lo[0], lo[1], lo[2], lo[3]);
    }

    // stage B: B[n][k] = Kmat[k][gy*128+n] (transposed load; Kmat is 128 KB, L2-resident)
    #pragma unroll
    for (int it = 0; it < 8; it++) {
        int idx = it * 256 + t;
        int n = idx >> 4;
        int k0 = (idx & 15) * 8;
        float x[8];
        #pragma unroll
        for (int i = 0; i < 8; i++)
            x[i] = __ldg(&Kmat[(size_t)(k0 + i) * CDIM + gy * 128 + n]);
        uint32_t hi[4], lo[4];
        #pragma unroll
        for (int p = 0; p < 4; p++) split2(x[2*p], x[2*p+1], hi[p], lo[p]);
        uint32_t off = (uint32_t)n * RSTR + (uint32_t)k0 * 2;
        *(uint4*)(smem + SB_HI + off) = make_uint4(hi[0], hi[1], hi[2], hi[3]);
        *(uint4*)(smem + SB_LO + off) = make_uint4(lo[0], lo[1], lo[2], lo[3]);
    }
    __syncthreads();

    // warp tile: 4 m-warps x 2 n-warps; each warp 32m x 64n
    int warp_m = wid & 3, warp_n = wid >> 2;
    int m0 = warp_m * 32, n0 = warp_n * 64;

    float acc[2][8][4];
    #pragma unroll
    for (int s = 0; s < 2; s++)
        #pragma unroll
        for (int f = 0; f < 8; f++)
            #pragma unroll
            for (int e = 0; e < 4; e++) acc[s][f][e] = 0.f;

    int lrow = lane & 15, lk = lane >> 4;      // A ldmatrix lane addressing
    int brow = lane & 7,  bk = (lane >> 3) & 1; // B ldmatrix lane addressing

    const uint32_t pa[3] = {SA_HI, SA_HI, SA_LO};
    const uint32_t pb[3] = {SB_HI, SB_LO, SB_HI};

    #pragma unroll
    for (int pass = 0; pass < 3; pass++) {
        uint32_t Abase = sb + pa[pass];
        uint32_t Bbase = sb + pb[pass];
        #pragma unroll
        for (int ks = 0; ks < 8; ks++) {
            uint32_t a0[4], a1[4], b[8][2];
            uint32_t aaddr = Abase + (uint32_t)(m0 + lrow) * RSTR + ks * 32 + lk * 16;
            LDM_X4(a0[0], a0[1], a0[2], a0[3], aaddr);
            LDM_X4(a1[0], a1[1], a1[2], a1[3], aaddr + 16u * RSTR);
            #pragma unroll
            for (int f = 0; f < 8; f++) {
                uint32_t baddr = Bbase + (uint32_t)(n0 + f * 8 + brow) * RSTR + ks * 32 + bk * 16;
                LDM_X2(b[f][0], b[f][1], baddr);
            }
            #pragma unroll
            for (int f = 0; f < 8; f++) {
                MMA_BF16(acc[0][f], a0, b[f]);
                MMA_BF16(acc[1][f], a1, b[f]);
            }
        }
    }

    // epilogue: add bias, contract with S over j = n&15, quad-reduce, store agg
    float p[2][2][4];
    #pragma unroll
    for (int s = 0; s < 2; s++)
        #pragma unroll
        for (int rh = 0; rh < 2; rh++)
            #pragma unroll
            for (int ii = 0; ii < 4; ii++) p[s][rh][ii] = 0.f;

    #pragma unroll
    for (int s = 0; s < 2; s++)
        #pragma unroll
        for (int f = 0; f < 8; f++)
            #pragma unroll
            for (int e = 0; e < 4; e++) {
                int n = n0 + f * 8 + (lane & 3) * 2 + (e & 1);
                int m = m0 + s * 16 + (lane >> 2) + (e >> 1) * 8;
                float c = acc[s][f][e] + bs[n];
                p[s][e >> 1][f >> 1] += c * Ss[m * 17 + (n & 15)];
            }

    #pragma unroll
    for (int s = 0; s < 2; s++)
        #pragma unroll
        for (int rh = 0; rh < 2; rh++)
            #pragma unroll
            for (int ii = 0; ii < 4; ii++) {
                float v = p[s][rh][ii];
                v += __shfl_xor_sync(0xffffffffu, v, 1);
                v += __shfl_xor_sync(0xffffffffu, v, 2);
                if ((lane & 3) == 0) {
                    int m = m0 + s * 16 + (lane >> 2) + rh * 8;
                    if (v0 + m < N_NODES) {
                        int ig = gy * 8 + warp_n * 4 + ii;
                        g_agg[(size_t)(v0 + m) * BD + ig] = v;
                    }
                }
            }
}

// ---------------- kernel 5: out = relu(agg@Wn + relu(bonds@Wi)) x4 ----------------
__global__ void k_final(const float* __restrict__ bonds,
                        const float* __restrict__ Wn,
                        const float* __restrict__ Wi,
                        float* __restrict__ out) {
    int h   = threadIdx.x & 127;
    int sub = threadIdx.x >> 7;
    int v0  = blockIdx.x * 16;
    float wn[16], wi[16];
    #pragma unroll
    for (int i = 0; i < 16; i++) {
        wn[i] = Wn[i * HID + h];
        wi[i] = Wi[i * HID + h];
    }
    const size_t slab = (size_t)N_NODES * HID;
    for (int q = 0; q < 8; q++) {
        int v = v0 + sub * 8 + q;
        if (v >= N_NODES) break;
        float nodes = 0.f, edge = 0.f;
        #pragma unroll
        for (int i = 0; i < 16; i++) {
            nodes += g_agg[(size_t)v * BD + i] * wn[i];
            edge  += __ldg(&bonds[(size_t)v * BD + i]) * wi[i];
        }
        edge = fmaxf(edge, 0.f);
        float r = fmaxf(nodes + edge, 0.f);
        size_t base = (size_t)v * HID + h;
        out[base]            = r;
        out[base + slab]     = r;
        out[base + 2 * slab] = r;
        out[base + 3 * slab] = r;
    }
}

// ---------------- launch ----------------
extern "C" void kernel_launch(void* const* d_in, const int* in_sizes, int n_in,
                              void* d_out, int out_size) {
    const float* atoms = (const float*)d_in[0];
    const float* bonds = (const float*)d_in[1];
    const void*  pairs = d_in[2];
    const float* Kmat  = (const float*)d_in[3];
    const float* bias  = (const float*)d_in[4];
    const float* Wn    = (const float*)d_in[5];
    const float* Wi    = (const float*)d_in[6];
    float* out = (float*)d_out;

    // unconditional (no static guards — harness rule); not a stream op, capture-safe
    cudaFuncSetAttribute(k_gemm_mma, cudaFuncAttributeMaxDynamicSharedMemorySize, SM_TOTAL);

    k_detect<<<1, 256>>>((const unsigned int*)pairs);
    k_convert<<<(N_EDGES + 255) / 256, 256>>>(pairs);
    k_off<<<(N_NODES + 256) / 256, 256>>>(pairs);
    k_S<<<N_NODES / 8, 256>>>(bonds);
    dim3 g3((N_NODES + 127) / 128, 2);
    k_gemm_mma<<<g3, 256, SM_TOTAL>>>(atoms, Kmat, bias);
    k_final<<<(N_NODES + 15) / 16, 256>>>(bonds, Wn, Wi, out);
}